// round 1
// baseline (speedup 1.0000x reference)
#include <cuda_runtime.h>
#include <math.h>

// Problem constants
#define B_    2048
#define T_    128
#define D_    20
#define H_    128
#define STEPS 127          // T-1
#define KE    148          // H + D extended contraction
#define RPB   14           // batch rows per block
#define NBLK  147          // ceil(2048/14)

// Scratch (allocation-free: __device__ globals)
__device__ float4 g_wpack[KE * H_];   // [k][u] = {W_i, W_f, W_g, W_o} at contraction index k
__device__ float4 g_bias4[H_];        // combined b_ih + b_hh per unit, 4 gates
__device__ float  g_alpha[B_ * D_];   // softmax(xw) per batch row

// ---------------------------------------------------------------------------
// K0: pack weights k-major as float4 per (k, unit); combine biases.
// k < 128 -> W_hh[:, k]; k >= 128 -> W_ih[:, k-128]
// ---------------------------------------------------------------------------
__global__ void pack_kernel(const float* __restrict__ W_ih,
                            const float* __restrict__ W_hh,
                            const float* __restrict__ b_ih,
                            const float* __restrict__ b_hh) {
    int u = threadIdx.x;       // 0..127
    int k = blockIdx.x;        // 0..147
    float4 w;
    if (k < H_) {
        w.x = W_hh[(0 * H_ + u) * H_ + k];
        w.y = W_hh[(1 * H_ + u + 0) * H_ + k + 0];  // j = 128 + u
        w.y = W_hh[(128 + u) * H_ + k];
        w.z = W_hh[(256 + u) * H_ + k];
        w.w = W_hh[(384 + u) * H_ + k];
    } else {
        int d = k - H_;
        w.x = W_ih[(u)       * D_ + d];
        w.y = W_ih[(128 + u) * D_ + d];
        w.z = W_ih[(256 + u) * D_ + d];
        w.w = W_ih[(384 + u) * D_ + d];
    }
    g_wpack[k * H_ + u] = w;
    if (k == 0) {
        g_bias4[u] = make_float4(b_ih[u]       + b_hh[u],
                                 b_ih[128 + u] + b_hh[128 + u],
                                 b_ih[256 + u] + b_hh[256 + u],
                                 b_ih[384 + u] + b_hh[384 + u]);
    }
}

// ---------------------------------------------------------------------------
// K1: per batch row b, xw[d] = sum_t X[b,t,d]*w_x[t]; alpha = softmax_d(xw).
// (hs is a per-row scalar -> shifts cancel in softmax, so alpha is constant
//  over timesteps.) Also writes the entire X_tilde output = alpha * X[:, :127].
// One warp per batch row.
// ---------------------------------------------------------------------------
__global__ void __launch_bounds__(256, 1)
attn_kernel(const float* __restrict__ X,
            const float* __restrict__ W_attn,
            float* __restrict__ out_xt) {
    __shared__ float wx_s[T_];
    int tid = threadIdx.x;
    for (int i = tid; i < T_; i += 256) wx_s[i] = W_attn[2 * H_ + i];
    __syncthreads();

    int b    = (blockIdx.x * 256 + tid) >> 5;
    int lane = tid & 31;
    if (b >= B_) return;

    const float* xb = X + (long)b * T_ * D_;
    float acc = 0.f;
    if (lane < D_) {
        #pragma unroll 4
        for (int t = 0; t < T_; t++) acc = fmaf(xb[t * D_ + lane], wx_s[t], acc);
    }
    float v = (lane < D_) ? acc : -INFINITY;
    #pragma unroll
    for (int off = 16; off; off >>= 1) v = fmaxf(v, __shfl_xor_sync(0xffffffffu, v, off));
    float e = (lane < D_) ? __expf(acc - v) : 0.f;
    float s = e;
    #pragma unroll
    for (int off = 16; off; off >>= 1) s += __shfl_xor_sync(0xffffffffu, s, off);
    float alpha = e / s;

    if (lane < D_) {
        g_alpha[b * D_ + lane] = alpha;
        for (int t = 0; t < STEPS; t++)
            out_xt[((long)b * STEPS + t) * D_ + lane] = alpha * xb[t * D_ + lane];
    }
}

// ---------------------------------------------------------------------------
// K2: persistent LSTM. One block owns RPB=14 batch rows for all 127 steps.
// Thread (u = tid&127, half = tid>>7) computes all 4 gates of hidden unit u
// for 7 rows. c lives in registers; h (+ staged x_tilde) lives in SMEM.
// gates[r][g*128+u] = bias + sum_{k<148} wpack[k][u].g * hx[r][k]
// ---------------------------------------------------------------------------
__device__ __forceinline__ float sigf(float x) {
    return 1.f / (1.f + __expf(-x));
}

__global__ void __launch_bounds__(256, 1)
lstm_main(const float* __restrict__ X, float* __restrict__ out_enc) {
    __shared__ float hx[RPB][KE];        // [row][k]: k<128 = h, k>=128 = x_tilde
    __shared__ float alpha_s[RPB][D_];

    int tid  = threadIdx.x;
    int u    = tid & 127;
    int half = tid >> 7;                  // 0 or 1: rows [half*7, half*7+7)
    int row0 = blockIdx.x * RPB;

    for (int i = tid; i < RPB * D_; i += 256) {
        int r = i / D_, d = i % D_;
        alpha_s[r][d] = (row0 + r < B_) ? g_alpha[(row0 + r) * D_ + d] : 0.f;
    }
    for (int i = tid; i < RPB * KE; i += 256) hx[i / KE][i % KE] = 0.f;

    float4 bias = g_bias4[u];
    float c[7];
    #pragma unroll
    for (int r = 0; r < 7; r++) c[r] = 0.f;
    __syncthreads();

    const float4* __restrict__ wp = g_wpack + u;

    for (int t = 0; t < STEPS; t++) {
        // stage x_tilde[r][d] = alpha[r][d] * X[b, t, d]
        for (int i = tid; i < RPB * D_; i += 256) {
            int r = i / D_, d = i % D_;
            int b = row0 + r;
            float xv = (b < B_) ? X[(b * T_ + t) * D_ + d] : 0.f;
            hx[r][H_ + d] = alpha_s[r][d] * xv;
        }
        __syncthreads();

        float a0[7], a1[7], a2[7], a3[7];
        #pragma unroll
        for (int r = 0; r < 7; r++) { a0[r] = bias.x; a1[r] = bias.y; a2[r] = bias.z; a3[r] = bias.w; }

        const float* hrow = &hx[half * 7][0];
        #pragma unroll 4
        for (int k = 0; k < KE; k++) {
            float4 w = wp[k * H_];
            #pragma unroll
            for (int r = 0; r < 7; r++) {
                float hv = hrow[r * KE + k];
                a0[r] = fmaf(w.x, hv, a0[r]);
                a1[r] = fmaf(w.y, hv, a1[r]);
                a2[r] = fmaf(w.z, hv, a2[r]);
                a3[r] = fmaf(w.w, hv, a3[r]);
            }
        }
        __syncthreads();   // all GEMM reads of hx done before h is overwritten

        #pragma unroll
        for (int r = 0; r < 7; r++) {
            int rg = half * 7 + r;
            float iv = sigf(a0[r]);
            float fv = sigf(a1[r]);
            float gv = tanhf(a2[r]);
            float ov = sigf(a3[r]);
            float cn = fmaf(fv, c[r], iv * gv);
            c[r] = cn;
            float hn = ov * tanhf(cn);
            hx[rg][u] = hn;
            int b = row0 + rg;
            if (b < B_) out_enc[((long)b * STEPS + t) * H_ + u] = hn;
        }
        __syncthreads();   // h writes visible before next step's GEMM
    }
}

// ---------------------------------------------------------------------------
extern "C" void kernel_launch(void* const* d_in, const int* in_sizes, int n_in,
                              void* d_out, int out_size) {
    const float* X      = (const float*)d_in[0];
    const float* W_attn = (const float*)d_in[1];
    // d_in[2] = b_attn: cancels in softmax, unused
    const float* W_ih   = (const float*)d_in[3];
    const float* W_hh   = (const float*)d_in[4];
    const float* b_ih   = (const float*)d_in[5];
    const float* b_hh   = (const float*)d_in[6];

    float* out     = (float*)d_out;
    float* out_xt  = out;                              // [B,127,20]
    float* out_enc = out + (long)B_ * STEPS * D_;      // [B,127,128]

    pack_kernel<<<KE, H_>>>(W_ih, W_hh, b_ih, b_hh);
    attn_kernel<<<(B_ * 32) / 256, 256>>>(X, W_attn, out_xt);
    lstm_main<<<NBLK, 256>>>(X, out_enc);
}

// round 3
// speedup vs baseline: 1.1843x; 1.1843x over previous
#include <cuda_runtime.h>
#include <math.h>

#define B_    2048
#define T_    128
#define D_    20
#define H_    128
#define STEPS 127          // T-1
#define KE    148          // H + D extended contraction
#define RPB   16           // batch rows per block (2048 = 16 * 128)
#define NBLK  128
#define HPAD  20           // padded row-stride of k-major hx (80B: 16B-aligned LDS.128)

typedef unsigned long long u64;

// Scratch (allocation-free: __device__ globals)
__device__ float4 g_wpack[KE * H_];   // [k][u] = {W_i, W_f, W_g, W_o}
__device__ float4 g_bias4[H_];        // combined b_ih + b_hh per unit
__device__ float  g_alpha[B_ * D_];   // softmax(xw) per batch row

// ---------------------------------------------------------------------------
__device__ __forceinline__ u64 ffma2(u64 a, u64 b, u64 c) {
    u64 d;
    asm("fma.rn.f32x2 %0, %1, %2, %3;" : "=l"(d) : "l"(a), "l"(b), "l"(c));
    return d;
}
__device__ __forceinline__ u64 dup2(float x) {
    u64 d;
    asm("mov.b64 %0, {%1, %1};" : "=l"(d) : "f"(x));
    return d;
}
__device__ __forceinline__ float sigf(float x) {
    return __frcp_rn(1.f + __expf(-x));
}
__device__ __forceinline__ float tanhfast(float x) {
    // tanh(x) = 1 - 2/(exp(2x)+1); saturates correctly at +/-inf
    return fmaf(-2.f, __frcp_rn(__expf(2.f * x) + 1.f), 1.f);
}

// ---------------------------------------------------------------------------
// K0: pack weights k-major as float4 per (k, unit); combine biases.
// k < 128 -> W_hh[:, k]; k >= 128 -> W_ih[:, k-128]
// ---------------------------------------------------------------------------
__global__ void pack_kernel(const float* __restrict__ W_ih,
                            const float* __restrict__ W_hh,
                            const float* __restrict__ b_ih,
                            const float* __restrict__ b_hh) {
    int u = threadIdx.x;       // 0..127
    int k = blockIdx.x;        // 0..147
    float4 w;
    if (k < H_) {
        w.x = W_hh[(u)       * H_ + k];
        w.y = W_hh[(128 + u) * H_ + k];
        w.z = W_hh[(256 + u) * H_ + k];
        w.w = W_hh[(384 + u) * H_ + k];
    } else {
        int d = k - H_;
        w.x = W_ih[(u)       * D_ + d];
        w.y = W_ih[(128 + u) * D_ + d];
        w.z = W_ih[(256 + u) * D_ + d];
        w.w = W_ih[(384 + u) * D_ + d];
    }
    g_wpack[k * H_ + u] = w;
    if (k == 0) {
        g_bias4[u] = make_float4(b_ih[u]       + b_hh[u],
                                 b_ih[128 + u] + b_hh[128 + u],
                                 b_ih[256 + u] + b_hh[256 + u],
                                 b_ih[384 + u] + b_hh[384 + u]);
    }
}

// ---------------------------------------------------------------------------
// K1: alpha = softmax_d(sum_t X[b,t,d] * w_x[t]) (hs is a per-row scalar so
// it cancels in the softmax -> alpha is timestep-invariant).
// Writes the full X_tilde output for all 127 steps. One warp per batch row.
// ---------------------------------------------------------------------------
__global__ void __launch_bounds__(256, 1)
attn_kernel(const float* __restrict__ X,
            const float* __restrict__ W_attn,
            float* __restrict__ out_xt) {
    __shared__ float wx_s[T_];
    int tid = threadIdx.x;
    for (int i = tid; i < T_; i += 256) wx_s[i] = W_attn[2 * H_ + i];
    __syncthreads();

    int b    = (blockIdx.x * 256 + tid) >> 5;
    int lane = tid & 31;
    if (b >= B_) return;

    const float* xb = X + (long)b * T_ * D_;
    float acc = 0.f;
    if (lane < D_) {
        #pragma unroll 4
        for (int t = 0; t < T_; t++) acc = fmaf(xb[t * D_ + lane], wx_s[t], acc);
    }
    float v = (lane < D_) ? acc : -INFINITY;
    #pragma unroll
    for (int off = 16; off; off >>= 1) v = fmaxf(v, __shfl_xor_sync(0xffffffffu, v, off));
    float e = (lane < D_) ? __expf(acc - v) : 0.f;
    float s = e;
    #pragma unroll
    for (int off = 16; off; off >>= 1) s += __shfl_xor_sync(0xffffffffu, s, off);
    float alpha = e / s;

    if (lane < D_) {
        g_alpha[b * D_ + lane] = alpha;
        for (int t = 0; t < STEPS; t++)
            out_xt[((long)b * STEPS + t) * D_ + lane] = alpha * xb[t * D_ + lane];
    }
}

// ---------------------------------------------------------------------------
// K2: persistent LSTM with packed f32x2 math.
// Block owns 16 batch rows. Thread (u = tid&127, half = tid>>7) computes all
// 4 gates of unit u for 8 rows = 4 f32x2 row-pairs. hx is k-major in SMEM
// (row stride HPAD=20 floats = 80B -> every LDS.128 is 16B aligned; all
// lanes of a warp read the same address -> broadcast, conflict-free).
// ---------------------------------------------------------------------------
__global__ void __launch_bounds__(256, 1)
lstm_main(const float* __restrict__ X, float* __restrict__ out_enc) {
    __shared__ __align__(16) float hxT[KE * HPAD];  // [k][row]

    int tid  = threadIdx.x;
    int u    = tid & 127;
    int half = tid >> 7;
    int row0 = blockIdx.x * RPB;

    // zero h + x regions
    for (int i = tid; i < KE * HPAD; i += 256) hxT[i] = 0.f;

    // staging assignment: thread covers slot tid and tid+256 of the 16*20=320
    int sr0 = tid / D_,         sd0 = tid % D_;            // always valid (tid<256<320)
    int sr1 = (tid + 256) / D_, sd1 = (tid + 256) % D_;
    bool s1ok = (tid + 256) < RPB * D_;
    const float* xp0 = X + ((long)(row0 + sr0) * T_) * D_ + sd0;
    const float* xp1 = s1ok ? X + ((long)(row0 + sr1) * T_) * D_ + sd1 : X;
    float al0 = g_alpha[(row0 + sr0) * D_ + sd0];
    float al1 = s1ok ? g_alpha[(row0 + sr1) * D_ + sd1] : 0.f;

    // stage x_tilde for t = 0
    hxT[(H_ + sd0) * HPAD + sr0] = al0 * xp0[0];
    if (s1ok) hxT[(H_ + sd1) * HPAD + sr1] = al1 * xp1[0];

    float4 b4 = g_bias4[u];
    u64 bias2[4] = { dup2(b4.x), dup2(b4.y), dup2(b4.z), dup2(b4.w) };

    float c[8];
    #pragma unroll
    for (int r = 0; r < 8; r++) c[r] = 0.f;

    const float4* __restrict__ wp = g_wpack + u;
    // out base: this thread's 8 rows start at global row row0 + half*8
    float* ob = out_enc + ((long)(row0 + half * 8) * STEPS) * H_ + u;
    const int rowstride = STEPS * H_;
    const int hoff = half * 8;

    __syncthreads();

    for (int t = 0; t < STEPS; t++) {
        u64 acc0[4], acc1[4], acc2[4], acc3[4];   // [row-pair][gate]
        #pragma unroll
        for (int g = 0; g < 4; g++) { acc0[g] = bias2[g]; acc1[g] = bias2[g]; acc2[g] = bias2[g]; acc3[g] = bias2[g]; }

        // 4-deep software-pipelined weight stream (KE = 148 = 37*4)
        float4 w0 = __ldg(&wp[0 * H_]);
        float4 w1 = __ldg(&wp[1 * H_]);
        float4 w2 = __ldg(&wp[2 * H_]);
        float4 w3 = __ldg(&wp[3 * H_]);

        #pragma unroll 1
        for (int k = 0; k < KE; k += 4) {
            float4 wa = w0, wb = w1, wc = w2, wd = w3;
            if (k + 4 < KE) {
                w0 = __ldg(&wp[(k + 4) * H_]);
                w1 = __ldg(&wp[(k + 5) * H_]);
                w2 = __ldg(&wp[(k + 6) * H_]);
                w3 = __ldg(&wp[(k + 7) * H_]);
            }
            #pragma unroll
            for (int j = 0; j < 4; j++) {
                float4 w = (j == 0) ? wa : (j == 1) ? wb : (j == 2) ? wc : wd;
                const ulonglong2 hv = *(const ulonglong2*)(hxT + (k + j) * HPAD + hoff);
                const ulonglong2 hw = *(const ulonglong2*)(hxT + (k + j) * HPAD + hoff + 4);
                u64 dx = dup2(w.x), dy = dup2(w.y), dz = dup2(w.z), dw = dup2(w.w);
                acc0[0] = ffma2(dx, hv.x, acc0[0]);
                acc0[1] = ffma2(dy, hv.x, acc0[1]);
                acc0[2] = ffma2(dz, hv.x, acc0[2]);
                acc0[3] = ffma2(dw, hv.x, acc0[3]);
                acc1[0] = ffma2(dx, hv.y, acc1[0]);
                acc1[1] = ffma2(dy, hv.y, acc1[1]);
                acc1[2] = ffma2(dz, hv.y, acc1[2]);
                acc1[3] = ffma2(dw, hv.y, acc1[3]);
                acc2[0] = ffma2(dx, hw.x, acc2[0]);
                acc2[1] = ffma2(dy, hw.x, acc2[1]);
                acc2[2] = ffma2(dz, hw.x, acc2[2]);
                acc2[3] = ffma2(dw, hw.x, acc2[3]);
                acc3[0] = ffma2(dx, hw.y, acc3[0]);
                acc3[1] = ffma2(dy, hw.y, acc3[1]);
                acc3[2] = ffma2(dz, hw.y, acc3[2]);
                acc3[3] = ffma2(dw, hw.y, acc3[3]);
            }
        }
        __syncthreads();   // all GEMM reads of hxT done before it is rewritten

        // epilogue: 4 row-pairs -> 8 rows
        #pragma unroll
        for (int p = 0; p < 4; p++) {
            u64 ai = (p == 0) ? acc0[0] : (p == 1) ? acc1[0] : (p == 2) ? acc2[0] : acc3[0];
            u64 af = (p == 0) ? acc0[1] : (p == 1) ? acc1[1] : (p == 2) ? acc2[1] : acc3[1];
            u64 ag = (p == 0) ? acc0[2] : (p == 1) ? acc1[2] : (p == 2) ? acc2[2] : acc3[2];
            u64 ao = (p == 0) ? acc0[3] : (p == 1) ? acc1[3] : (p == 2) ? acc2[3] : acc3[3];
            float2 fi = *(float2*)&ai;
            float2 ff = *(float2*)&af;
            float2 fg = *(float2*)&ag;
            float2 fo = *(float2*)&ao;
            #pragma unroll
            for (int j = 0; j < 2; j++) {
                int r = 2 * p + j;
                float iv = sigf(j ? fi.y : fi.x);
                float fv = sigf(j ? ff.y : ff.x);
                float gv = tanhfast(j ? fg.y : fg.x);
                float ov = sigf(j ? fo.y : fo.x);
                float cn = fmaf(fv, c[r], iv * gv);
                c[r] = cn;
                float hn = ov * tanhfast(cn);
                hxT[u * HPAD + hoff + r] = hn;
                ob[(long)r * rowstride + (long)t * H_] = hn;
            }
        }

        // stage x_tilde for t+1
        if (t + 1 < STEPS) {
            hxT[(H_ + sd0) * HPAD + sr0] = al0 * xp0[(t + 1) * D_];
            if (s1ok) hxT[(H_ + sd1) * HPAD + sr1] = al1 * xp1[(t + 1) * D_];
        }
        __syncthreads();   // h + x_tilde visible before next GEMM
    }
}

// ---------------------------------------------------------------------------
extern "C" void kernel_launch(void* const* d_in, const int* in_sizes, int n_in,
                              void* d_out, int out_size) {
    const float* X      = (const float*)d_in[0];
    const float* W_attn = (const float*)d_in[1];
    // d_in[2] = b_attn: cancels in softmax, unused
    const float* W_ih   = (const float*)d_in[3];
    const float* W_hh   = (const float*)d_in[4];
    const float* b_ih   = (const float*)d_in[5];
    const float* b_hh   = (const float*)d_in[6];

    float* out     = (float*)d_out;
    float* out_xt  = out;                              // [B,127,20]
    float* out_enc = out + (long)B_ * STEPS * D_;      // [B,127,128]

    pack_kernel<<<KE, H_>>>(W_ih, W_hh, b_ih, b_hh);
    attn_kernel<<<(B_ * 32) / 256, 256>>>(X, W_attn, out_xt);
    lstm_main<<<NBLK, 256>>>(X, out_enc);
}